// round 1
// baseline (speedup 1.0000x reference)
#include <cuda_runtime.h>
#include <cstddef>

#define NPTS   640000
#define NCAM   6
#define HH     512
#define WW     1408
#define NPIX   (HH * WW)          // 720896 = 2816 * 256
#define NCH    17
#define CSTRIDE 20                // pad 17 -> 20 so pixel base is 16B aligned
#define VOXS   0.4f

// 6 * 720896 * 20 * 4B = 346 MB scratch logit images (one per camera)
__device__ float  g_img[(size_t)NCAM * NPIX * CSTRIDE];
__device__ double g_num[NCAM];
__device__ double g_den[NCAM];

// ---------------------------------------------------------------------------
// Vectorized global reductions (sm_90+): 4 channels per LTS transaction
// ---------------------------------------------------------------------------
__device__ __forceinline__ void red_add_v4(float* addr, float a, float b, float c, float d) {
    asm volatile("red.global.add.v4.f32 [%0], {%1, %2, %3, %4};"
                 :: "l"(addr), "f"(a), "f"(b), "f"(c), "f"(d) : "memory");
}
__device__ __forceinline__ void red_add_f32(float* addr, float a) {
    asm volatile("red.global.add.f32 [%0], %1;"
                 :: "l"(addr), "f"(a) : "memory");
}

// ---------------------------------------------------------------------------
// 1) Zero scratch image + per-camera accumulators
// ---------------------------------------------------------------------------
__global__ void zero_kernel() {
    const size_t n4 = ((size_t)NCAM * NPIX * CSTRIDE) / 4;
    float4 z4 = make_float4(0.f, 0.f, 0.f, 0.f);
    float4* p = reinterpret_cast<float4*>(g_img);
    for (size_t i = (size_t)blockIdx.x * blockDim.x + threadIdx.x; i < n4;
         i += (size_t)gridDim.x * blockDim.x)
        p[i] = z4;
    if (blockIdx.x == 0 && threadIdx.x < NCAM) {
        g_num[threadIdx.x] = 0.0;
        g_den[threadIdx.x] = 0.0;
    }
}

// ---------------------------------------------------------------------------
// 2) Splat: one thread per point, loop over cameras (feats reused in regs)
// ---------------------------------------------------------------------------
__global__ void __launch_bounds__(256)
splat_kernel(const float* __restrict__ xyz,
             const float* __restrict__ feats,
             const float* __restrict__ opac,
             const float* __restrict__ vm,
             const float* __restrict__ Ks) {
    int i = blockIdx.x * blockDim.x + threadIdx.x;
    if (i >= NPTS) return;

    const float X = xyz[3 * i + 0];
    const float Y = xyz[3 * i + 1];
    const float Z = xyz[3 * i + 2];
    const float op = opac[i];

    float f[NCH];
#pragma unroll
    for (int c = 0; c < NCH; c++) f[c] = feats[(size_t)i * NCH + c];

    const float s2 = VOXS * VOXS;

#pragma unroll 1
    for (int cam = 0; cam < NCAM; cam++) {
        const float* M = vm + cam * 16;  // (4,4) row-major
        float p0 = M[0] * X + M[1] * Y + M[2]  * Z + M[3];
        float p1 = M[4] * X + M[5] * Y + M[6]  * Z + M[7];
        float p2 = M[8] * X + M[9] * Y + M[10] * Z + M[11];
        if (!(p2 > 0.1f)) continue;  // matches reference validity

        const float* K = Ks + cam * 9;   // (3,3) row-major
        const float fx = K[0], cx = K[2], fy = K[4], cy = K[5];

        float z  = fmaxf(p2, 0.001f);
        float iz = 1.0f / z;
        float u  = fx * p0 * iz + cx;
        float v  = fy * p1 * iz + cy;

        float j00 = fx * iz, j11 = fy * iz;
        float j02 = -fx * p0 * iz * iz;
        float j12 = -fy * p1 * iz * iz;
        float a = s2 * (j00 * j00 + j02 * j02) + 0.3f;
        float b = s2 * (j02 * j12);
        float c = s2 * (j11 * j11 + j12 * j12) + 0.3f;
        float idet = 1.0f / (a * c - b * b);
        float ca = c * idet, cb = -b * idet, cc = a * idet;

        float ru = rintf(u);  // round-half-even == jnp.round
        float rv = rintf(v);
        // Whole 3x3 footprint outside image -> skip
        if (ru < -1.0f || ru > (float)WW || rv < -1.0f || rv > (float)HH) continue;

#pragma unroll
        for (int ky = 0; ky < 3; ky++) {
            float py = rv + (float)(ky - 1);
            if (py < 0.0f || py >= (float)HH) continue;
            float ddy = py - v;
#pragma unroll
            for (int kx = 0; kx < 3; kx++) {
                float px = ru + (float)(kx - 1);
                if (px < 0.0f || px >= (float)WW) continue;
                float ddx = px - u;
                float e = -0.5f * (ca * ddx * ddx + 2.0f * cb * ddx * ddy + cc * ddy * ddy);
                float w = op * __expf(e);

                float* base = g_img +
                    ((size_t)cam * NPIX + (size_t)((int)py * WW + (int)px)) * CSTRIDE;
                red_add_v4(base + 0,  w * f[0],  w * f[1],  w * f[2],  w * f[3]);
                red_add_v4(base + 4,  w * f[4],  w * f[5],  w * f[6],  w * f[7]);
                red_add_v4(base + 8,  w * f[8],  w * f[9],  w * f[10], w * f[11]);
                red_add_v4(base + 12, w * f[12], w * f[13], w * f[14], w * f[15]);
                red_add_f32(base + 16, w * f[16]);
            }
        }
    }
}

// ---------------------------------------------------------------------------
// 3) Per-pixel log-softmax + weighted NLL, block-reduced into double accums
// ---------------------------------------------------------------------------
__global__ void __launch_bounds__(256)
loss_kernel(const int* __restrict__ gt, const float* __restrict__ cw) {
    const int BLOCKS_PER_CAM = NPIX / 256;  // 2816, exact
    int cam = blockIdx.x / BLOCKS_PER_CAM;
    int pix = (blockIdx.x % BLOCKS_PER_CAM) * 256 + threadIdx.x;

    const float* L = g_img + ((size_t)cam * NPIX + pix) * CSTRIDE;
    float l[NCH];
#pragma unroll
    for (int c = 0; c < NCH; c++) l[c] = L[c];

    float m = l[0];
#pragma unroll
    for (int c = 1; c < NCH; c++) m = fmaxf(m, l[c]);
    float s = 0.0f;
#pragma unroll
    for (int c = 0; c < NCH; c++) s += __expf(l[c] - m);
    float lse = m + __logf(s);

    int g = gt[(size_t)cam * NPIX + pix];
    float w = (g != 0) ? cw[g] : 0.0f;
    float num = w * (lse - l[g]);

    __shared__ float sn[256], sd[256];
    sn[threadIdx.x] = num;
    sd[threadIdx.x] = w;
    __syncthreads();
#pragma unroll
    for (int st = 128; st > 0; st >>= 1) {
        if (threadIdx.x < st) {
            sn[threadIdx.x] += sn[threadIdx.x + st];
            sd[threadIdx.x] += sd[threadIdx.x + st];
        }
        __syncthreads();
    }
    if (threadIdx.x == 0) {
        atomicAdd(&g_num[cam], (double)sn[0]);
        atomicAdd(&g_den[cam], (double)sd[0]);
    }
}

// ---------------------------------------------------------------------------
// 4) Finalize: loss = mean_cam( num / max(den, 1e-8) )
// ---------------------------------------------------------------------------
__global__ void finalize_kernel(float* out) {
    if (threadIdx.x == 0 && blockIdx.x == 0) {
        double acc = 0.0;
        for (int cam = 0; cam < NCAM; cam++) {
            double d = g_den[cam];
            if (d < 1e-8) d = 1e-8;
            acc += g_num[cam] / d;
        }
        out[0] = (float)(acc / (double)NCAM);
    }
}

// ---------------------------------------------------------------------------
extern "C" void kernel_launch(void* const* d_in, const int* in_sizes, int n_in,
                              void* d_out, int out_size) {
    const float* voxel_feats = (const float*)d_in[0];   // (1,200,200,16,17)
    const float* density     = (const float*)d_in[1];   // (1,200,200,16,1)
    const float* viewmats    = (const float*)d_in[2];   // (1,6,4,4)
    const float* Ks          = (const float*)d_in[3];   // (1,6,3,3)
    const int*   gt_sem      = (const int*)d_in[4];     // (1,6,512,1408)
    const float* pc_xyz      = (const float*)d_in[5];   // (640000,3)
    const float* cw          = (const float*)d_in[6];   // (17,)
    float* out = (float*)d_out;

    zero_kernel<<<2048, 256>>>();
    splat_kernel<<<(NPTS + 255) / 256, 256>>>(pc_xyz, voxel_feats, density, viewmats, Ks);
    loss_kernel<<<NCAM * (NPIX / 256), 256>>>(gt_sem, cw);
    finalize_kernel<<<1, 1>>>(out);
}